// round 11
// baseline (speedup 1.0000x reference)
#include <cuda_runtime.h>

// Persistent-kernel TV denoiser (Chambolle-Pock, RHO-relaxed), single launch.
// 592 blocks (= 148 SMs x 4 CTAs) x 128 threads; each thread owns 4 adjacent
// columns (float4) and marches a 6/7-row stripe that never crosses an image.
// One grid barrier per iteration; the LAST block through the barrier computes
// the (deterministic, fixed-order) convergence decision and broadcasts it.

#define WW 512
#define HH 512
#define IMG (HH*WW)
#define BATCH 8
#define NTOT (BATCH*IMG)
#define NTHR 128
#define NWARP (NTHR/32)
#define BPI 74                   // blocks per image
#define NBLK (BATCH*BPI)         // 592 = 148*4, all co-resident
#define NB7 68                   // stripes 0..67: 7 rows; 68..73: 6 rows

#define TAUc     0.01f
#define INV1PTAU (1.0f/1.01f)
#define SIGMAc   12.5f
#define RHOc     1.99f
#define HRHOc    0.995f          /* RHO/2 */
#define THSc     0.1f
#define THS2c    0.01f           /* THS^2 */
#define CRITc    1e-5f
#define NITERc   40

__device__ float g_x [2][NTOT];
__device__ float g_u0[2][NTOT];
__device__ float g_u1[2][NTOT];
__device__ float g_pnum[NBLK];
__device__ float g_pden[NBLK];
__device__ volatile float        g_sdec;
__device__ unsigned int          g_count = 0;
__device__ volatile unsigned int g_gen   = 0;

// z = 2x - x2 for this thread's 4 columns in one row, plus the lane-31 fixup
// column (c+4). nl: row has a down-diff (row != 511). u0prev/u0fixprev:
// previous-row u0 (registers / 0 at image top). Warp shuffles inside: call
// only with block-uniform control.
__device__ __forceinline__ void row_quad(
    const float* __restrict__ xin, const float* __restrict__ u0in,
    const float* __restrict__ u1in, const float* __restrict__ yv,
    int g, int tid, int lane, bool cfixOK, bool nl,
    float4 u0prev, float u0fixprev,
    float4& u0c, float4& u1c, float4& x2c,
    float4& z, float& zf, float& u0fc)
{
    u0c = *(const float4*)(u0in + g);
    u1c = *(const float4*)(u1in + g);
    x2c = *(const float4*)(xin  + g);
    float4 yc = *(const float4*)(yv + g);

    float u1left = __shfl_up_sync(0xffffffffu, u1c.w, 1);
    if (lane == 0) u1left = (tid > 0) ? u1in[g - 1] : 0.f;

    float u0x = nl ? u0c.x : 0.f;
    float u0y = nl ? u0c.y : 0.f;
    float u0z = nl ? u0c.z : 0.f;
    float u0w = nl ? u0c.w : 0.f;
    float u1w = (tid == NTHR - 1) ? 0.f : u1c.w;   // col 511: no right diff

    float ax = u0prev.x + u1left - u0x - u1c.x;
    float ay = u0prev.y + u1c.x  - u0y - u1c.y;
    float az = u0prev.z + u1c.y  - u0z - u1c.z;
    float aw = u0prev.w + u1c.z  - u0w - u1w;

    float x0 = fmaf(TAUc, yc.x - ax, x2c.x) * INV1PTAU;
    float x1 = fmaf(TAUc, yc.y - ay, x2c.y) * INV1PTAU;
    float x2 = fmaf(TAUc, yc.z - az, x2c.z) * INV1PTAU;
    float x3 = fmaf(TAUc, yc.w - aw, x2c.w) * INV1PTAU;
    z.x = 2.f * x0 - x2c.x;
    z.y = 2.f * x1 - x2c.y;
    z.z = 2.f * x2 - x2c.z;
    z.w = 2.f * x3 - x2c.w;

    zf = 0.f; u0fc = 0.f;
    if (cfixOK) {                       // lane 31 (not tid 127): column c+4
        float u0f = u0in[g + 4];
        float u1f = u1in[g + 4];
        float x2f = xin [g + 4];
        float yf  = yv  [g + 4];
        float u0fx = nl ? u0f : 0.f;
        float af = u0fixprev + u1c.w - u0fx - u1f;
        float xf = fmaf(TAUc, yf - af, x2f) * INV1PTAU;
        zf = 2.f * xf - x2f;
        u0fc = u0f;
    }
}

template<int NR>
__device__ __forceinline__ void do_rows(
    const float* __restrict__ xin, const float* __restrict__ u0in,
    const float* __restrict__ u1in, const float* __restrict__ yv,
    float* __restrict__ xout, float* __restrict__ u0out,
    float* __restrict__ u1out,
    int g0, int i0, bool isTop, bool notBottom, int tid, int lane, bool cfixOK,
    float& num, float& den)
{
    const float4 zz = make_float4(0.f, 0.f, 0.f, 0.f);

    // prologue: row i0 (i0 <= 506, so nl is always true here)
    float4 u0prev = isTop ? zz : *(const float4*)(u0in + g0 - WW);
    float u0fixprev = (cfixOK && !isTop) ? u0in[g0 + 4 - WW] : 0.f;

    float4 u0c, u1c, x2c, z;
    float zfc, u0fc;
    row_quad(xin, u0in, u1in, yv, g0, tid, lane, cfixOK, true,
             u0prev, u0fixprev, u0c, u1c, x2c, z, zfc, u0fc);

    int g = g0;
    #pragma unroll
    for (int r = 0; r < NR; r++) {
        // row i0+r has a down-diff unless it is row 511 (bottom stripe, last r)
        const bool nl = (r < NR - 1) || notBottom;

        float4 u0N = zz, u1N = zz, x2N = zz, zN = zz;
        float zfN = 0.f, u0fN = 0.f;
        if (nl) {                                    // block-uniform
            const bool nlN = (i0 + r + 1) != (HH - 1);
            row_quad(xin, u0in, u1in, yv, g + WW, tid, lane, cfixOK, nlN,
                     u0c, u0fc, u0N, u1N, x2N, zN, zfN, u0fN);
        }

        float zsh = __shfl_down_sync(0xffffffffu, z.x, 1);
        float zr  = (lane == 31) ? zfc : zsh;
        float dwx = z.y - z.x;
        float dwy = z.z - z.y;
        float dwz = z.w - z.z;
        float dww = (tid == NTHR - 1) ? 0.f : (zr - z.w);

        float dhx = nl ? (zN.x - z.x) : 0.f;
        float dhy = nl ? (zN.y - z.y) : 0.f;
        float dhz = nl ? (zN.z - z.z) : 0.f;
        float dhw = nl ? (zN.w - z.w) : 0.f;

        float v0x = fmaf(SIGMAc, dhx, u0c.x);
        float v0y = fmaf(SIGMAc, dhy, u0c.y);
        float v0z = fmaf(SIGMAc, dhz, u0c.z);
        float v0w = fmaf(SIGMAc, dhw, u0c.w);
        float v1x = fmaf(SIGMAc, dwx, u1c.x);
        float v1y = fmaf(SIGMAc, dwy, u1c.y);
        float v1z = fmaf(SIGMAc, dwz, u1c.z);
        float v1w = fmaf(SIGMAc, dww, u1c.w);

        float m2x = fmaf(v0x, v0x, v1x * v1x);
        float m2y = fmaf(v0y, v0y, v1y * v1y);
        float m2z = fmaf(v0z, v0z, v1z * v1z);
        float m2w = fmaf(v0w, v0w, v1w * v1w);
        float scx = (m2x > THS2c) ? (THSc * rsqrtf(m2x)) : 1.f;
        float scy = (m2y > THS2c) ? (THSc * rsqrtf(m2y)) : 1.f;
        float scz = (m2z > THS2c) ? (THSc * rsqrtf(m2z)) : 1.f;
        float scw = (m2w > THS2c) ? (THSc * rsqrtf(m2w)) : 1.f;

        float4 xn, u0n, u1n;
        xn.x  = fmaf(HRHOc, z.x - x2c.x, x2c.x);
        xn.y  = fmaf(HRHOc, z.y - x2c.y, x2c.y);
        xn.z  = fmaf(HRHOc, z.z - x2c.z, x2c.z);
        xn.w  = fmaf(HRHOc, z.w - x2c.w, x2c.w);
        u0n.x = fmaf(RHOc, fmaf(v0x, scx, -u0c.x), u0c.x);
        u0n.y = fmaf(RHOc, fmaf(v0y, scy, -u0c.y), u0c.y);
        u0n.z = fmaf(RHOc, fmaf(v0z, scz, -u0c.z), u0c.z);
        u0n.w = fmaf(RHOc, fmaf(v0w, scw, -u0c.w), u0c.w);
        u1n.x = fmaf(RHOc, fmaf(v1x, scx, -u1c.x), u1c.x);
        u1n.y = fmaf(RHOc, fmaf(v1y, scy, -u1c.y), u1c.y);
        u1n.z = fmaf(RHOc, fmaf(v1z, scz, -u1c.z), u1c.z);
        u1n.w = fmaf(RHOc, fmaf(v1w, scw, -u1c.w), u1c.w);

        *(float4*)(xout  + g) = xn;
        *(float4*)(u0out + g) = u0n;
        *(float4*)(u1out + g) = u1n;

        float d0 = xn.x - x2c.x, d1 = xn.y - x2c.y;
        float d2 = xn.z - x2c.z, d3 = xn.w - x2c.w;
        num = fmaf(d0, d0, num);  num = fmaf(d1, d1, num);
        num = fmaf(d2, d2, num);  num = fmaf(d3, d3, num);
        float e0 = xn.x + 1e-12f, e1 = xn.y + 1e-12f;
        float e2 = xn.z + 1e-12f, e3 = xn.w + 1e-12f;
        den = fmaf(e0, e0, den);  den = fmaf(e1, e1, den);
        den = fmaf(e2, e2, den);  den = fmaf(e3, e3, den);

        u0c = u0N; u1c = u1N; x2c = x2N;
        z = zN; zfc = zfN; u0fc = u0fN;
        g += WW;
    }
}

__global__ void __launch_bounds__(NTHR, 4)
tv_persistent(const float* __restrict__ yv, float* __restrict__ out)
{
    const int tid  = threadIdx.x;
    const int lane = tid & 31;
    const int wid  = tid >> 5;
    const int blk  = blockIdx.x;
    const bool cfixOK = (lane == 31) && (tid != NTHR - 1);

    const int b = blk / BPI;            // image
    const int s = blk - b * BPI;        // stripe within image (0..73)
    const int nrows = (s < NB7) ? 7 : 6;
    const int i0 = (s < NB7) ? (7 * s) : (7 * NB7 + 6 * (s - NB7));
    const bool isTop     = (s == 0);
    const bool notBottom = (s != BPI - 1);
    const int g0 = b * IMG + i0 * WW + 4 * tid;

    __shared__ float snum[NWARP], sden[NWARP];
    __shared__ unsigned int s_gen;
    __shared__ int s_last;

    // ---- init own stripe: x2 = y, u = 0 ----
    {
        int gg = g0;
        const float4 zz = make_float4(0.f, 0.f, 0.f, 0.f);
        for (int r = 0; r < nrows; r++, gg += WW) {
            *(float4*)(g_x [0] + gg) = *(const float4*)(yv + gg);
            *(float4*)(g_u0[0] + gg) = zz;
            *(float4*)(g_u1[0] + gg) = zz;
        }
    }

    int executed = NITERc;

    for (int t = 0; t <= NITERc; t++) {
        // ================= barrier (+ decision by the last block) ==========
        // Entered with this block's iteration-(t-1) writes pending (or init).
        __threadfence();
        __syncthreads();
        if (tid == 0) {
            s_gen  = g_gen;
            s_last = (atomicInc(&g_count, NBLK - 1u) == NBLK - 1u) ? 1 : 0;
        }
        __syncthreads();
        const bool have_stats = (t >= 3);   // partials of iter t-1 exist from t-1>=2
        if (s_last) {
            if (have_stats) {
                __threadfence();            // invalidate L1: partials are fresh
                float n2 = 0.f, d2 = 0.f;
                #pragma unroll
                for (int k = 0; k < (NBLK + NTHR - 1) / NTHR; k++) {
                    int idx = tid + k * NTHR;
                    if (idx < NBLK) { n2 += g_pnum[idx]; d2 += g_pden[idx]; }
                }
                #pragma unroll
                for (int o = 16; o; o >>= 1) {
                    n2 += __shfl_down_sync(0xffffffffu, n2, o);
                    d2 += __shfl_down_sync(0xffffffffu, d2, o);
                }
                if (lane == 0) { snum[wid] = n2; sden[wid] = d2; }
                __syncthreads();
                if (tid == 0) {
                    float N = 0.f, D = 0.f;
                    #pragma unroll
                    for (int w = 0; w < NWARP; w++) { N += snum[w]; D += sden[w]; }
                    g_sdec = sqrtf(N) / sqrtf(D);
                }
            }
            __threadfence();                // order g_sdec before release
            __syncthreads();
            if (tid == 0) g_gen = s_gen + 1u;
        } else {
            if (tid == 0) { while (g_gen == s_gen) __nanosleep(32); }
        }
        __syncthreads();
        __threadfence();                    // invalidate L1: fresh halos + g_sdec

        if (have_stats) {
            float dec = g_sdec;             // volatile broadcast read
            if (dec < CRITc) { executed = t - 1 + 1; break; }  // = (t-1)+1
        }
        if (t == NITERc) break;             // all iterations done

        // ================= iteration t =====================================
        const int p = t & 1;
        const float* __restrict__ xin  = g_x [p];
        const float* __restrict__ u0in = g_u0[p];
        const float* __restrict__ u1in = g_u1[p];
        float* __restrict__ xout  = g_x [p ^ 1];
        float* __restrict__ u0out = g_u0[p ^ 1];
        float* __restrict__ u1out = g_u1[p ^ 1];

        float num = 0.f, den = 0.f;
        if (nrows == 7)
            do_rows<7>(xin, u0in, u1in, yv, xout, u0out, u1out,
                       g0, i0, isTop, notBottom, tid, lane, cfixOK, num, den);
        else
            do_rows<6>(xin, u0in, u1in, yv, xout, u0out, u1out,
                       g0, i0, isTop, notBottom, tid, lane, cfixOK, num, den);

        // -- publish convergence partials (needed from t >= 2) --
        if (t >= 2) {
            #pragma unroll
            for (int o = 16; o; o >>= 1) {
                num += __shfl_down_sync(0xffffffffu, num, o);
                den += __shfl_down_sync(0xffffffffu, den, o);
            }
            if (lane == 0) { snum[wid] = num; sden[wid] = den; }
            __syncthreads();
            if (tid == 0) {
                float n2 = 0.f, d2 = 0.f;
                #pragma unroll
                for (int w = 0; w < NWARP; w++) { n2 += snum[w]; d2 += sden[w]; }
                g_pnum[blk] = n2;
                g_pden[blk] = d2;
            }
            __syncthreads();   // protect snum/sden reuse at next barrier
        }
    }

    // ---- write own stripe from the buffer holding the final state ----
    const float* __restrict__ src = g_x[executed & 1];
    int gg = g0;
    for (int r = 0; r < nrows; r++, gg += WW)
        *(float4*)(out + gg) = *(const float4*)(src + gg);
}

extern "C" void kernel_launch(void* const* d_in, const int* in_sizes, int n_in,
                              void* d_out, int out_size) {
    const float* y = (const float*)d_in[0];
    float* out = (float*)d_out;
    tv_persistent<<<NBLK, NTHR>>>(y, out);
}